// round 13
// baseline (speedup 1.0000x reference)
#include <cuda_runtime.h>
#include <math.h>

#define BATCH 16384
#define DIM 64
#define LAMBDA 0.01f
#define TPB 256
#define GRID (BATCH / 16)               // 1024 blocks, 16 rows/block
#define CNT_SHIFT 54
#define FIX_SCALE 16777216.0f           // 2^24
#define FIX_INV   (1.0f / 16777216.0f)

// packed accumulator: bits[63:54] = completed-block count, bits[53:0] = fixed-point sum
__device__ unsigned long long g_pack = 0ull;

__global__ void __launch_bounds__(TPB) pmf_kernel(
    const int* __restrict__ u,
    const int* __restrict__ iidx,
    const int* __restrict__ s,
    const float4* __restrict__ W4,   // [USER_SIZE * 16]
    const float4* __restrict__ H4,   // [ITEM_SIZE * 16]
    float* __restrict__ out)
{
    const int tid  = threadIdx.x;
    const int grp  = tid >> 4;          // 0..15
    const int lane = tid & 15;          // 0..15
    const int row  = blockIdx.x * 16 + grp;

    const int ur = __ldg(&u[row]);
    const int ir = __ldg(&iidx[row]);
    int sv = 0;
    if (lane == 0) sv = __ldg(&s[row]);

    // two independent 16B gathers per thread
    const float4 a = __ldg(&W4[(size_t)ur * 16 + lane]);
    const float4 b = __ldg(&H4[(size_t)ir * 16 + lane]);

    float dot = a.x * b.x + a.y * b.y + a.z * b.z + a.w * b.w;
    float reg = LAMBDA * (a.x * a.x + a.y * a.y + a.z * a.z + a.w * a.w
                        + b.x * b.x + b.y * b.y + b.z * b.z + b.w * b.w);

    #pragma unroll
    for (int off = 8; off >= 1; off >>= 1) {
        dot += __shfl_down_sync(0xFFFFFFFFu, dot, off);
        reg += __shfl_down_sync(0xFFFFFFFFu, reg, off);
    }

    __shared__ float sdata[16];
    if (lane == 0) {
        float x  = dot;
        float ls = fminf(x, 0.0f) - log1pf(expf(-fabsf(x)));   // stable log-sigmoid
        float d  = (float)sv - ls;
        sdata[grp] = d * d + reg;                              // strictly positive
    }
    __syncthreads();

    if (tid < 16) {
        float v = sdata[tid];
        #pragma unroll
        for (int off = 8; off >= 1; off >>= 1)
            v += __shfl_down_sync(0xFFFFu, v, off);
        if (tid == 0) {
            // single relaxed 64-bit atomic: payload carries both count and sum,
            // so no fences / release / acquire are needed anywhere.
            const unsigned long long mine =
                (1ull << CNT_SHIFT) | (unsigned long long)__float2ll_rn(v * FIX_SCALE);
            const unsigned long long old = atomicAdd(&g_pack, mine);
            if ((old >> CNT_SHIFT) == (unsigned long long)(GRID - 1)) {
                // we are the last block: old+mine holds the complete packed total
                const unsigned long long total = old + mine;
                const long long fix = (long long)(total & ((1ull << CNT_SHIFT) - 1ull));
                out[0] = (float)fix * FIX_INV * (1.0f / (float)BATCH);
                g_pack = 0ull;   // reset for next graph replay (ordered by launch boundary)
            }
        }
    }
}

extern "C" void kernel_launch(void* const* d_in, const int* in_sizes, int n_in,
                              void* d_out, int out_size) {
    const int*   u = (const int*)d_in[0];
    const int*   i = (const int*)d_in[1];
    const int*   s = (const int*)d_in[2];
    const float* W = (const float*)d_in[3];
    const float* H = (const float*)d_in[4];
    float* out = (float*)d_out;

    pmf_kernel<<<GRID, TPB>>>(u, i, s,
                              (const float4*)W, (const float4*)H, out);
}